// round 16
// baseline (speedup 1.0000x reference)
#include <cuda_runtime.h>
#include <cuda_fp16.h>
#include <cstdint>
#include <math.h>

#define BB   4
#define NQ   384
#define NK   384
#define DQI  256
#define DKI  256
#define DM   64
#define DFF  256
#define DOUT 64
#define KT   64      // k-rows per CTA

#define SROW 528     // H row stride bytes (16B-aligned, mod 128 = 16 -> LDSM conflict-free)

#define OFF_H   0                      // 64 x 528 = 33792 (X cols 0..127h, h cols 0..255h)
#define OFF_AQ  33792                  // 1024
#define OFF_QS  34816                  // 768
#define OFF_B2  35584                  // 256
#define SMEM_BYTES 35840

#define PREP_G  4                      // items per prep block
#define NBQ     (BB * NQ / PREP_G)     // 384

// ---------------- device scratch ----------------
__device__ float  g_Aq[BB * NQ * DFF];   // fp32, exact
// Bk packed as mma-D-fragment uint4s: [ktile16][ngroup][lane][4]
__device__ uint4 g_Bkp[(BB * NK / 16) * 4 * 32 * 4];      // 768 KB
// per-thread mma B fragments: [ks][npair][lane] -> uint4 {b0,b1 | b0,b1}
__device__ uint4 g_W1f[8 * 16 * 32];    // 64 KB  (W1 rows 128..255, n 0..255)
__device__ uint4 g_W2f[16 * 4 * 32];    // 32 KB  (W2 k 0..255, n 0..63)

// ---------------- helpers ----------------
__device__ __forceinline__ uint32_t smem_u32(const void* p) {
    uint32_t a;
    asm("{ .reg .u64 t; cvta.to.shared.u64 t, %1; cvt.u32.u64 %0, t; }" : "=r"(a) : "l"(p));
    return a;
}
__device__ __forceinline__ void ldsm4(uint32_t* r, uint32_t addr) {
    asm volatile("ldmatrix.sync.aligned.m8n8.x4.shared.b16 {%0,%1,%2,%3}, [%4];"
        : "=r"(r[0]), "=r"(r[1]), "=r"(r[2]), "=r"(r[3]) : "r"(addr));
}
__device__ __forceinline__ void mma16(float* d, const uint32_t* a, uint32_t b0, uint32_t b1) {
    asm volatile(
        "mma.sync.aligned.m16n8k16.row.col.f32.f16.f16.f32 "
        "{%0,%1,%2,%3}, {%4,%5,%6,%7}, {%8,%9}, {%0,%1,%2,%3};"
        : "+f"(d[0]), "+f"(d[1]), "+f"(d[2]), "+f"(d[3])
        : "r"(a[0]), "r"(a[1]), "r"(a[2]), "r"(a[3]), "r"(b0), "r"(b1));
}
// silu(v) = 0.5v + 0.5v*tanh(0.5v)
__device__ __forceinline__ float silu_f(float v) {
    float hv = 0.5f * v, th;
    asm("tanh.approx.f32 %0, %1;" : "=f"(th) : "f"(hv));
    return fmaf(hv, th, hv);
}
__device__ __forceinline__ uint32_t h2u(__half2 h) { return *(uint32_t*)&h; }

// ---------------- merged prep kernel: 4 items per block, R12-shaped loads ----------------
// blocks [0,384): Aq x4 ; [384,768): Bk x4 ; [768,792): weight fragments
__global__ void prep_all(const float* __restrict__ q_inv, const float* __restrict__ Wq,
                         const float* __restrict__ bq, const float* __restrict__ W1,
                         const float* __restrict__ b1,
                         const float* __restrict__ k_inv, const float* __restrict__ Wk,
                         const float* __restrict__ bk, const float* __restrict__ W2) {
    const int bx = blockIdx.x, tid = threadIdx.x;
    __shared__ float sv[DQI];
    __shared__ float sm[DM];

    if (bx < NBQ) {
        // ---- Aq for 4 consecutive q items ----
        #pragma unroll 1
        for (int it = 0; it < PREP_G; ++it) {
            const int bqi = bx * PREP_G + it;
            sv[tid] = q_inv[(size_t)bqi * DQI + tid];
            __syncthreads();
            if (tid < DM) {   // stage 1: coalesced Wq columns, 8-wide MLP
                float a0 = 0.f, a1 = 0.f, a2 = 0.f, a3 = 0.f;
                float a4 = 0.f, a5 = 0.f, a6 = 0.f, a7 = 0.f;
                #pragma unroll 8
                for (int i = 0; i < DQI; i += 8) {
                    a0 += sv[i]     * Wq[(size_t)i * DM + tid];
                    a1 += sv[i + 1] * Wq[(size_t)(i + 1) * DM + tid];
                    a2 += sv[i + 2] * Wq[(size_t)(i + 2) * DM + tid];
                    a3 += sv[i + 3] * Wq[(size_t)(i + 3) * DM + tid];
                    a4 += sv[i + 4] * Wq[(size_t)(i + 4) * DM + tid];
                    a5 += sv[i + 5] * Wq[(size_t)(i + 5) * DM + tid];
                    a6 += sv[i + 6] * Wq[(size_t)(i + 6) * DM + tid];
                    a7 += sv[i + 7] * Wq[(size_t)(i + 7) * DM + tid];
                }
                sm[tid] = bq[tid] + (((a0 + a1) + (a2 + a3)) + ((a4 + a5) + (a6 + a7)));
            }
            __syncthreads();
            {   // stage 2
                float a0 = 0.f, a1 = 0.f, a2 = 0.f, a3 = 0.f;
                float a4 = 0.f, a5 = 0.f, a6 = 0.f, a7 = 0.f;
                #pragma unroll 8
                for (int m = 0; m < DM; m += 8) {
                    a0 += sm[m]     * W1[(size_t)m * DFF + tid];
                    a1 += sm[m + 1] * W1[(size_t)(m + 1) * DFF + tid];
                    a2 += sm[m + 2] * W1[(size_t)(m + 2) * DFF + tid];
                    a3 += sm[m + 3] * W1[(size_t)(m + 3) * DFF + tid];
                    a4 += sm[m + 4] * W1[(size_t)(m + 4) * DFF + tid];
                    a5 += sm[m + 5] * W1[(size_t)(m + 5) * DFF + tid];
                    a6 += sm[m + 6] * W1[(size_t)(m + 6) * DFF + tid];
                    a7 += sm[m + 7] * W1[(size_t)(m + 7) * DFF + tid];
                }
                g_Aq[(size_t)bqi * DFF + tid] =
                    b1[tid] + (((a0 + a1) + (a2 + a3)) + ((a4 + a5) + (a6 + a7)));
            }
            __syncthreads();
        }
    } else if (bx < 2 * NBQ) {
        // ---- Bk (packed) for 4 consecutive k items ----
        #pragma unroll 1
        for (int it = 0; it < PREP_G; ++it) {
            const int bki = (bx - NBQ) * PREP_G + it;
            sv[tid] = k_inv[(size_t)bki * DKI + tid];
            __syncthreads();
            if (tid < DM) {
                float a0 = 0.f, a1 = 0.f, a2 = 0.f, a3 = 0.f;
                float a4 = 0.f, a5 = 0.f, a6 = 0.f, a7 = 0.f;
                #pragma unroll 8
                for (int i = 0; i < DKI; i += 8) {
                    a0 += sv[i]     * Wk[(size_t)i * DM + tid];
                    a1 += sv[i + 1] * Wk[(size_t)(i + 1) * DM + tid];
                    a2 += sv[i + 2] * Wk[(size_t)(i + 2) * DM + tid];
                    a3 += sv[i + 3] * Wk[(size_t)(i + 3) * DM + tid];
                    a4 += sv[i + 4] * Wk[(size_t)(i + 4) * DM + tid];
                    a5 += sv[i + 5] * Wk[(size_t)(i + 5) * DM + tid];
                    a6 += sv[i + 6] * Wk[(size_t)(i + 6) * DM + tid];
                    a7 += sv[i + 7] * Wk[(size_t)(i + 7) * DM + tid];
                }
                sm[tid] = bk[tid] + (((a0 + a1) + (a2 + a3)) + ((a4 + a5) + (a6 + a7)));
            }
            __syncthreads();
            {
                float a0 = 0.f, a1 = 0.f, a2 = 0.f, a3 = 0.f;
                float a4 = 0.f, a5 = 0.f, a6 = 0.f, a7 = 0.f;
                #pragma unroll 8
                for (int m = 0; m < DM; m += 8) {
                    a0 += sm[m]     * W1[(size_t)(64 + m) * DFF + tid];
                    a1 += sm[m + 1] * W1[(size_t)(65 + m) * DFF + tid];
                    a2 += sm[m + 2] * W1[(size_t)(66 + m) * DFF + tid];
                    a3 += sm[m + 3] * W1[(size_t)(67 + m) * DFF + tid];
                    a4 += sm[m + 4] * W1[(size_t)(68 + m) * DFF + tid];
                    a5 += sm[m + 5] * W1[(size_t)(69 + m) * DFF + tid];
                    a6 += sm[m + 6] * W1[(size_t)(70 + m) * DFF + tid];
                    a7 += sm[m + 7] * W1[(size_t)(71 + m) * DFF + tid];
                }
                float val = (((a0 + a1) + (a2 + a3)) + ((a4 + a5) + (a6 + a7)));
                const int kt16 = bki >> 4, hf = (bki >> 3) & 1, g = bki & 7;
                const int lane = g * 4 + ((tid >> 1) & 3);
                const int ngroup = tid >> 6, ni = (tid & 63) >> 3;
                const int u = hf * 2 + (ni >> 2);
                size_t hidx = ((((size_t)(kt16 * 4 + ngroup) * 32 + lane) * 4 + u) * 8)
                              + (ni & 3) * 2 + (tid & 1);
                ((__half*)g_Bkp)[hidx] = __float2half_rn(val);
            }
            __syncthreads();
        }
    } else {
        // ---- weight fragments ----
        const int idx = (bx - 2 * NBQ) * 256 + tid;
        if (idx < 8 * 16 * 32) {
            int ks = idx >> 9, npair = (idx >> 5) & 15, lane = idx & 31;
            int k0 = 128 + ks * 16 + 2 * (lane & 3);
            int na = npair * 16 + (lane >> 2), nb = na + 8;
            uint4 u;
            u.x = h2u(__floats2half2_rn(W1[(size_t)k0 * DFF + na],       W1[(size_t)(k0 + 1) * DFF + na]));
            u.y = h2u(__floats2half2_rn(W1[(size_t)(k0 + 8) * DFF + na], W1[(size_t)(k0 + 9) * DFF + na]));
            u.z = h2u(__floats2half2_rn(W1[(size_t)k0 * DFF + nb],       W1[(size_t)(k0 + 1) * DFF + nb]));
            u.w = h2u(__floats2half2_rn(W1[(size_t)(k0 + 8) * DFF + nb], W1[(size_t)(k0 + 9) * DFF + nb]));
            g_W1f[idx] = u;
        } else if (idx < 8 * 16 * 32 + 16 * 4 * 32) {
            int h = idx - 8 * 16 * 32;
            int ks = h >> 7, npair = (h >> 5) & 3, lane = h & 31;
            int k0 = ks * 16 + 2 * (lane & 3);
            int na = npair * 16 + (lane >> 2), nb = na + 8;
            uint4 u;
            u.x = h2u(__floats2half2_rn(W2[(size_t)k0 * DOUT + na],       W2[(size_t)(k0 + 1) * DOUT + na]));
            u.y = h2u(__floats2half2_rn(W2[(size_t)(k0 + 8) * DOUT + na], W2[(size_t)(k0 + 9) * DOUT + na]));
            u.z = h2u(__floats2half2_rn(W2[(size_t)k0 * DOUT + nb],       W2[(size_t)(k0 + 1) * DOUT + nb]));
            u.w = h2u(__floats2half2_rn(W2[(size_t)(k0 + 8) * DOUT + nb], W2[(size_t)(k0 + 9) * DOUT + nb]));
            g_W2f[h] = u;
        }
    }
}

// ---------------- main kernel: one CTA = (b, q, 64-k tile), 3 CTAs/SM (R12 exact) ----------------
__global__ __launch_bounds__(256, 3)
void pm_main(const float* __restrict__ q_equi, const float* __restrict__ k_equi,
             const float* __restrict__ b2, float* __restrict__ out) {
    extern __shared__ char smem[];
    char* Hb = smem + OFF_H;
    float* Aqs = (float*)(smem + OFF_AQ);
    float* qs  = (float*)(smem + OFF_QS);
    float* b2s = (float*)(smem + OFF_B2);
    const uint32_t sb = smem_u32(smem);

    const int kb = blockIdx.x, q = blockIdx.y, b = blockIdx.z;
    const int kbase = kb * KT, bq = b * NQ + q;
    const int tid = threadIdx.x, w = tid >> 5, lane = tid & 31;
    const int g = lane >> 2, t = lane & 3;
    const int lrow = lane & 15, lsel = lane >> 4;

    // ---- stage qs / Aq / b2 ----
    if (tid < 192) qs[tid] = q_equi[(size_t)bq * 192 + tid];
    Aqs[tid] = g_Aq[(size_t)bq * DFF + tid];
    if (tid < 64) b2s[tid] = b2[tid];
    __syncthreads();

    // ---- build X = [dot | dist] fp16 (float4 lanes), 64 rows, stride 528 B ----
    {
        const int e4 = (tid & 15) * 4, kk0 = tid >> 4;
        const float4 q0 = *(const float4*)&qs[e4];
        const float4 q1 = *(const float4*)&qs[64 + e4];
        const float4 q2 = *(const float4*)&qs[128 + e4];
        const float qn0 = q0.x * q0.x + q1.x * q1.x + q2.x * q2.x;
        const float qn1 = q0.y * q0.y + q1.y * q1.y + q2.y * q2.y;
        const float qn2v = q0.z * q0.z + q1.z * q1.z + q2.z * q2.z;
        const float qn3 = q0.w * q0.w + q1.w * q1.w + q2.w * q2.w;
        const float* kp0 = k_equi + (size_t)(b * NK + kbase) * 192 + e4;
        #pragma unroll
        for (int j = 0; j < 4; j++) {
            int kk = kk0 + j * 16;
            const float* kp = kp0 + (size_t)kk * 192;
            float4 k0 = *(const float4*)kp;
            float4 k1 = *(const float4*)(kp + 64);
            float4 k2 = *(const float4*)(kp + 128);
            float d0 = q0.x * k0.x + q1.x * k1.x + q2.x * k2.x;
            float d1 = q0.y * k0.y + q1.y * k1.y + q2.y * k2.y;
            float d2 = q0.z * k0.z + q1.z * k1.z + q2.z * k2.z;
            float d3 = q0.w * k0.w + q1.w * k1.w + q2.w * k2.w;
            float n0v = k0.x * k0.x + k1.x * k1.x + k2.x * k2.x;
            float n1v = k0.y * k0.y + k1.y * k1.y + k2.y * k2.y;
            float n2v = k0.z * k0.z + k1.z * k1.z + k2.z * k2.z;
            float n3v = k0.w * k0.w + k1.w * k1.w + k2.w * k2.w;
            float s0 = sqrtf(fmaxf(qn0  + n0v - 2.f * d0, 0.f));
            float s1 = sqrtf(fmaxf(qn1  + n1v - 2.f * d1, 0.f));
            float s2 = sqrtf(fmaxf(qn2v + n2v - 2.f * d2, 0.f));
            float s3 = sqrtf(fmaxf(qn3  + n3v - 2.f * d3, 0.f));
            uint2 du, su;
            ((uint32_t*)&du)[0] = h2u(__floats2half2_rn(d0, d1));
            ((uint32_t*)&du)[1] = h2u(__floats2half2_rn(d2, d3));
            ((uint32_t*)&su)[0] = h2u(__floats2half2_rn(s0, s1));
            ((uint32_t*)&su)[1] = h2u(__floats2half2_rn(s2, s3));
            *(uint2*)(Hb + kk * SROW + e4 * 2)       = du;
            *(uint2*)(Hb + kk * SROW + 128 + e4 * 2) = su;
        }
    }
    __syncthreads();

    // ---- GEMM1 in two N-phases (32-reg accumulators), warps 2M x 4N of 32x32 ----
    const int m0 = (w >> 2) * 32, nw = (w & 3) * 32;
    const uint32_t aAddr = sb + OFF_H + (m0 + lrow) * SROW + lsel * 16;
    const int kt16a = (b * NK + kbase + m0) >> 4;       // ktile16 for mi=0
    const int half = (nw >> 5) & 1;                      // which half of 64-group

    #pragma unroll
    for (int ph = 1; ph >= 0; ph--) {                    // ph=1: cols 128..255 ; ph=0: cols 0..127
        const int nbase = ph * 128 + nw;
        float c1[2][4][4];
        #pragma unroll
        for (int mi = 0; mi < 2; mi++)
            #pragma unroll
            for (int ni = 0; ni < 4; ni++)
                #pragma unroll
                for (int z = 0; z < 4; z++) c1[mi][ni][z] = 0.f;

        const uint4* __restrict__ w1f = g_W1f + (nbase >> 4) * 32 + lane;
        #pragma unroll 2
        for (int ks = 0; ks < 8; ks++) {
            uint32_t a[2][4];
            ldsm4(a[0], aAddr + ks * 32);
            ldsm4(a[1], aAddr + 16 * SROW + ks * 32);
            #pragma unroll
            for (int p = 0; p < 2; p++) {
                uint4 f = w1f[ks * 512 + p * 32];
                mma16(c1[0][2 * p],     a[0], f.x, f.y);
                mma16(c1[1][2 * p],     a[1], f.x, f.y);
                mma16(c1[0][2 * p + 1], a[0], f.z, f.w);
                mma16(c1[1][2 * p + 1], a[1], f.z, f.w);
            }
        }

        if (ph == 0) __syncthreads();    // phase-B epilogue overwrites X: wait for all X reads

        // ---- epilogue: h = fp16(silu(D1 + Aq + Bk)) for this 128-col phase ----
        #pragma unroll
        for (int mi = 0; mi < 2; mi++) {
            const int r0 = m0 + mi * 16 + g, r1 = r0 + 8;
            const uint4* __restrict__ bp =
                g_Bkp + ((size_t)((kt16a + mi) * 4 + (nbase >> 6)) * 32 + lane) * 4;
            uint4 u0 = bp[half], u1 = bp[2 + half];
            const __half2* he0 = (const __half2*)&u0;
            const __half2* he1 = (const __half2*)&u1;
            #pragma unroll
            for (int ni = 0; ni < 4; ni++) {
                int f0 = nbase + 8 * ni + 2 * t;
                float2 aq = *(const float2*)(Aqs + f0);
                float2 e0 = __half22float2(he0[ni]);
                float2 e1 = __half22float2(he1[ni]);
                float v00 = silu_f(c1[mi][ni][0] + aq.x + e0.x);
                float v01 = silu_f(c1[mi][ni][1] + aq.y + e0.y);
                float v10 = silu_f(c1[mi][ni][2] + aq.x + e1.x);
                float v11 = silu_f(c1[mi][ni][3] + aq.y + e1.y);
                *(__half2*)(Hb + r0 * SROW + f0 * 2) = __floats2half2_rn(v00, v01);
                *(__half2*)(Hb + r1 * SROW + f0 * 2) = __floats2half2_rn(v10, v11);
            }
        }
    }
    __syncthreads();

    // ---- GEMM2: [64x256] @ [256x64], warps 4M x 2N, B from global fragments ----
    const int m2 = (w >> 1) * 16, n2 = (w & 1) * 32;
    float c2[4][4];
    #pragma unroll
    for (int ni = 0; ni < 4; ni++)
        #pragma unroll
        for (int z = 0; z < 4; z++) c2[ni][z] = 0.f;

    const uint32_t a2Addr = sb + OFF_H + (m2 + lrow) * SROW + lsel * 16;
    const uint4* __restrict__ w2f = g_W2f + (w & 1) * 64 + lane;

    #pragma unroll 4
    for (int ks = 0; ks < 16; ks++) {
        uint32_t a[4];
        ldsm4(a, a2Addr + ks * 32);
        #pragma unroll
        for (int p = 0; p < 2; p++) {
            uint4 f = w2f[ks * 128 + p * 32];
            mma16(c2[2 * p],     a, f.x, f.y);
            mma16(c2[2 * p + 1], a, f.z, f.w);
        }
    }

    // ---- epilogue 2: + b2 -> out ----
    const size_t obase = ((size_t)bq * NK + kbase) * DOUT;
    #pragma unroll
    for (int ni = 0; ni < 4; ni++) {
        int o = n2 + 8 * ni + 2 * t;
        int r0 = m2 + g, r1 = r0 + 8;
        *(float2*)(out + obase + (size_t)r0 * DOUT + o) =
            make_float2(c2[ni][0] + b2s[o], c2[ni][1] + b2s[o + 1]);
        *(float2*)(out + obase + (size_t)r1 * DOUT + o) =
            make_float2(c2[ni][2] + b2s[o], c2[ni][3] + b2s[o + 1]);
    }
}

// ---------------- launcher ----------------
extern "C" void kernel_launch(void* const* d_in, const int* in_sizes, int n_in,
                              void* d_out, int out_size) {
    const float* q_equi = (const float*)d_in[0];
    const float* q_inv  = (const float*)d_in[1];
    const float* k_equi = (const float*)d_in[2];
    const float* k_inv  = (const float*)d_in[3];
    const float* Wq     = (const float*)d_in[4];
    const float* bq     = (const float*)d_in[5];
    const float* Wk     = (const float*)d_in[6];
    const float* bk     = (const float*)d_in[7];
    const float* W1     = (const float*)d_in[8];
    const float* b1     = (const float*)d_in[9];
    const float* W2     = (const float*)d_in[10];
    const float* b2     = (const float*)d_in[11];
    float* out = (float*)d_out;

    cudaFuncSetAttribute(pm_main, cudaFuncAttributeMaxDynamicSharedMemorySize, SMEM_BYTES);

    prep_all<<<2 * NBQ + 24, 256>>>(q_inv, Wq, bq, W1, b1, k_inv, Wk, bk, W2);
    pm_main<<<dim3(NK / KT, NQ, BB), 256, SMEM_BYTES>>>(q_equi, k_equi, b2, out);
}

// round 17
// speedup vs baseline: 1.1382x; 1.1382x over previous
#include <cuda_runtime.h>
#include <cuda_fp16.h>
#include <cstdint>
#include <math.h>

#define BB   4
#define NQ   384
#define NK   384
#define DQI  256
#define DKI  256
#define DM   64
#define DFF  256
#define DOUT 64
#define KT   64      // k-rows per CTA

#define SROW 528     // H row stride bytes (16B-aligned, mod 128 = 16 -> LDSM conflict-free)

#define OFF_H   0                      // 64 x 528 = 33792 (X cols 0..127h, h cols 0..255h)
#define OFF_AQ  33792                  // 1024
#define OFF_QS  34816                  // 768
#define OFF_B2  35584                  // 256
#define SMEM_BYTES 35840

// ---------------- device scratch ----------------
__device__ float  g_Aq[BB * NQ * DFF];   // fp32, exact
// Bk packed as mma-D-fragment uint4s: [ktile16][ngroup][lane][4]
__device__ uint4 g_Bkp[(BB * NK / 16) * 4 * 32 * 4];      // 768 KB
// per-thread mma B fragments: [ks][npair][lane] -> uint4 {b0,b1 | b0,b1}
__device__ uint4 g_W1f[8 * 16 * 32];    // 64 KB  (W1 rows 128..255, n 0..255)
__device__ uint4 g_W2f[16 * 4 * 32];    // 32 KB  (W2 k 0..255, n 0..63)

// ---------------- helpers ----------------
__device__ __forceinline__ uint32_t smem_u32(const void* p) {
    uint32_t a;
    asm("{ .reg .u64 t; cvta.to.shared.u64 t, %1; cvt.u32.u64 %0, t; }" : "=r"(a) : "l"(p));
    return a;
}
__device__ __forceinline__ void ldsm4(uint32_t* r, uint32_t addr) {
    asm volatile("ldmatrix.sync.aligned.m8n8.x4.shared.b16 {%0,%1,%2,%3}, [%4];"
        : "=r"(r[0]), "=r"(r[1]), "=r"(r[2]), "=r"(r[3]) : "r"(addr));
}
__device__ __forceinline__ void mma16(float* d, const uint32_t* a, uint32_t b0, uint32_t b1) {
    asm volatile(
        "mma.sync.aligned.m16n8k16.row.col.f32.f16.f16.f32 "
        "{%0,%1,%2,%3}, {%4,%5,%6,%7}, {%8,%9}, {%0,%1,%2,%3};"
        : "+f"(d[0]), "+f"(d[1]), "+f"(d[2]), "+f"(d[3])
        : "r"(a[0]), "r"(a[1]), "r"(a[2]), "r"(a[3]), "r"(b0), "r"(b1));
}
// silu(v) = 0.5v + 0.5v*tanh(0.5v)
__device__ __forceinline__ float silu_f(float v) {
    float hv = 0.5f * v, th;
    asm("tanh.approx.f32 %0, %1;" : "=f"(th) : "f"(hv));
    return fmaf(hv, th, hv);
}
__device__ __forceinline__ uint32_t h2u(__half2 h) { return *(uint32_t*)&h; }

// ---------------- merged prep kernel: 1 item/block, quarter-split stage-1 ----------------
// blocks [0,1536): Aq ; [1536,3072): Bk packed ; [3072,3096): weight fragments
__global__ void prep_all(const float* __restrict__ q_inv, const float* __restrict__ Wq,
                         const float* __restrict__ bq, const float* __restrict__ W1,
                         const float* __restrict__ b1,
                         const float* __restrict__ k_inv, const float* __restrict__ Wk,
                         const float* __restrict__ bk, const float* __restrict__ W2) {
    const int bx = blockIdx.x, tid = threadIdx.x;
    __shared__ float sv[DQI];
    __shared__ float part[4][DM];
    __shared__ float sm[DM];

    if (bx < BB * NQ) {
        // ---- Aq for one q item ----
        const int bqi = bx;
        const int o = tid & 63, qt = tid >> 6;
        sv[tid] = q_inv[(size_t)bqi * DQI + tid];
        __syncthreads();
        // stage 1 (quarter-split, coalesced): part[qt][o] = sum_{i in quarter} sv[i]*Wq[i][o]
        {
            const float* wp = Wq + (size_t)(qt * 64) * DM + o;
            const float* sp = sv + qt * 64;
            float a0 = 0.f, a1 = 0.f, a2 = 0.f, a3 = 0.f;
            #pragma unroll 4
            for (int j = 0; j < 64; j += 4) {
                a0 += sp[j]     * wp[(size_t)j * DM];
                a1 += sp[j + 1] * wp[(size_t)(j + 1) * DM];
                a2 += sp[j + 2] * wp[(size_t)(j + 2) * DM];
                a3 += sp[j + 3] * wp[(size_t)(j + 3) * DM];
            }
            part[qt][o] = (a0 + a1) + (a2 + a3);
        }
        __syncthreads();
        if (tid < DM)
            sm[tid] = bq[tid] + ((part[0][tid] + part[1][tid]) + (part[2][tid] + part[3][tid]));
        __syncthreads();
        // stage 2: Aq[n] = b1[n] + sum_m sm[m]*W1[m][n]
        {
            float a0 = 0.f, a1 = 0.f, a2 = 0.f, a3 = 0.f;
            #pragma unroll 16
            for (int m = 0; m < DM; m += 4) {
                a0 += sm[m]     * W1[(size_t)m * DFF + tid];
                a1 += sm[m + 1] * W1[(size_t)(m + 1) * DFF + tid];
                a2 += sm[m + 2] * W1[(size_t)(m + 2) * DFF + tid];
                a3 += sm[m + 3] * W1[(size_t)(m + 3) * DFF + tid];
            }
            g_Aq[(size_t)bqi * DFF + tid] = b1[tid] + ((a0 + a1) + (a2 + a3));
        }
    } else if (bx < 2 * BB * NQ) {
        // ---- Bk (packed) for one k item ----
        const int bki = bx - BB * NQ;
        const int o = tid & 63, qt = tid >> 6;
        sv[tid] = k_inv[(size_t)bki * DKI + tid];
        __syncthreads();
        {
            const float* wp = Wk + (size_t)(qt * 64) * DM + o;
            const float* sp = sv + qt * 64;
            float a0 = 0.f, a1 = 0.f, a2 = 0.f, a3 = 0.f;
            #pragma unroll 4
            for (int j = 0; j < 64; j += 4) {
                a0 += sp[j]     * wp[(size_t)j * DM];
                a1 += sp[j + 1] * wp[(size_t)(j + 1) * DM];
                a2 += sp[j + 2] * wp[(size_t)(j + 2) * DM];
                a3 += sp[j + 3] * wp[(size_t)(j + 3) * DM];
            }
            part[qt][o] = (a0 + a1) + (a2 + a3);
        }
        __syncthreads();
        if (tid < DM)
            sm[tid] = bk[tid] + ((part[0][tid] + part[1][tid]) + (part[2][tid] + part[3][tid]));
        __syncthreads();
        {
            float a0 = 0.f, a1 = 0.f, a2 = 0.f, a3 = 0.f;
            #pragma unroll 16
            for (int m = 0; m < DM; m += 4) {
                a0 += sm[m]     * W1[(size_t)(64 + m) * DFF + tid];
                a1 += sm[m + 1] * W1[(size_t)(65 + m) * DFF + tid];
                a2 += sm[m + 2] * W1[(size_t)(66 + m) * DFF + tid];
                a3 += sm[m + 3] * W1[(size_t)(67 + m) * DFF + tid];
            }
            float val = (a0 + a1) + (a2 + a3);
            const int kt16 = bki >> 4, hf = (bki >> 3) & 1, g = bki & 7;
            const int lane = g * 4 + ((tid >> 1) & 3);
            const int ngroup = tid >> 6, ni = (tid & 63) >> 3;
            const int u = hf * 2 + (ni >> 2);
            size_t hidx = ((((size_t)(kt16 * 4 + ngroup) * 32 + lane) * 4 + u) * 8)
                          + (ni & 3) * 2 + (tid & 1);
            ((__half*)g_Bkp)[hidx] = __float2half_rn(val);
        }
    } else {
        // ---- weight fragments ----
        const int idx = (bx - 2 * BB * NQ) * 256 + tid;
        if (idx < 8 * 16 * 32) {
            int ks = idx >> 9, npair = (idx >> 5) & 15, lane = idx & 31;
            int k0 = 128 + ks * 16 + 2 * (lane & 3);
            int na = npair * 16 + (lane >> 2), nb = na + 8;
            uint4 u;
            u.x = h2u(__floats2half2_rn(W1[(size_t)k0 * DFF + na],       W1[(size_t)(k0 + 1) * DFF + na]));
            u.y = h2u(__floats2half2_rn(W1[(size_t)(k0 + 8) * DFF + na], W1[(size_t)(k0 + 9) * DFF + na]));
            u.z = h2u(__floats2half2_rn(W1[(size_t)k0 * DFF + nb],       W1[(size_t)(k0 + 1) * DFF + nb]));
            u.w = h2u(__floats2half2_rn(W1[(size_t)(k0 + 8) * DFF + nb], W1[(size_t)(k0 + 9) * DFF + nb]));
            g_W1f[idx] = u;
        } else if (idx < 8 * 16 * 32 + 16 * 4 * 32) {
            int h = idx - 8 * 16 * 32;
            int ks = h >> 7, npair = (h >> 5) & 3, lane = h & 31;
            int k0 = ks * 16 + 2 * (lane & 3);
            int na = npair * 16 + (lane >> 2), nb = na + 8;
            uint4 u;
            u.x = h2u(__floats2half2_rn(W2[(size_t)k0 * DOUT + na],       W2[(size_t)(k0 + 1) * DOUT + na]));
            u.y = h2u(__floats2half2_rn(W2[(size_t)(k0 + 8) * DOUT + na], W2[(size_t)(k0 + 9) * DOUT + na]));
            u.z = h2u(__floats2half2_rn(W2[(size_t)k0 * DOUT + nb],       W2[(size_t)(k0 + 1) * DOUT + nb]));
            u.w = h2u(__floats2half2_rn(W2[(size_t)(k0 + 8) * DOUT + nb], W2[(size_t)(k0 + 9) * DOUT + nb]));
            g_W2f[h] = u;
        }
    }
}

// ---------------- main kernel: one CTA = (b, q, 64-k tile), 3 CTAs/SM (R12 exact) ----------------
__global__ __launch_bounds__(256, 3)
void pm_main(const float* __restrict__ q_equi, const float* __restrict__ k_equi,
             const float* __restrict__ b2, float* __restrict__ out) {
    extern __shared__ char smem[];
    char* Hb = smem + OFF_H;
    float* Aqs = (float*)(smem + OFF_AQ);
    float* qs  = (float*)(smem + OFF_QS);
    float* b2s = (float*)(smem + OFF_B2);
    const uint32_t sb = smem_u32(smem);

    const int kb = blockIdx.x, q = blockIdx.y, b = blockIdx.z;
    const int kbase = kb * KT, bq = b * NQ + q;
    const int tid = threadIdx.x, w = tid >> 5, lane = tid & 31;
    const int g = lane >> 2, t = lane & 3;
    const int lrow = lane & 15, lsel = lane >> 4;

    // ---- stage qs / Aq / b2 ----
    if (tid < 192) qs[tid] = q_equi[(size_t)bq * 192 + tid];
    Aqs[tid] = g_Aq[(size_t)bq * DFF + tid];
    if (tid < 64) b2s[tid] = b2[tid];
    __syncthreads();

    // ---- build X = [dot | dist] fp16 (float4 lanes), 64 rows, stride 528 B ----
    {
        const int e4 = (tid & 15) * 4, kk0 = tid >> 4;
        const float4 q0 = *(const float4*)&qs[e4];
        const float4 q1 = *(const float4*)&qs[64 + e4];
        const float4 q2 = *(const float4*)&qs[128 + e4];
        const float qn0 = q0.x * q0.x + q1.x * q1.x + q2.x * q2.x;
        const float qn1 = q0.y * q0.y + q1.y * q1.y + q2.y * q2.y;
        const float qn2v = q0.z * q0.z + q1.z * q1.z + q2.z * q2.z;
        const float qn3 = q0.w * q0.w + q1.w * q1.w + q2.w * q2.w;
        const float* kp0 = k_equi + (size_t)(b * NK + kbase) * 192 + e4;
        #pragma unroll
        for (int j = 0; j < 4; j++) {
            int kk = kk0 + j * 16;
            const float* kp = kp0 + (size_t)kk * 192;
            float4 k0 = *(const float4*)kp;
            float4 k1 = *(const float4*)(kp + 64);
            float4 k2 = *(const float4*)(kp + 128);
            float d0 = q0.x * k0.x + q1.x * k1.x + q2.x * k2.x;
            float d1 = q0.y * k0.y + q1.y * k1.y + q2.y * k2.y;
            float d2 = q0.z * k0.z + q1.z * k1.z + q2.z * k2.z;
            float d3 = q0.w * k0.w + q1.w * k1.w + q2.w * k2.w;
            float n0v = k0.x * k0.x + k1.x * k1.x + k2.x * k2.x;
            float n1v = k0.y * k0.y + k1.y * k1.y + k2.y * k2.y;
            float n2v = k0.z * k0.z + k1.z * k1.z + k2.z * k2.z;
            float n3v = k0.w * k0.w + k1.w * k1.w + k2.w * k2.w;
            float s0 = sqrtf(fmaxf(qn0  + n0v - 2.f * d0, 0.f));
            float s1 = sqrtf(fmaxf(qn1  + n1v - 2.f * d1, 0.f));
            float s2 = sqrtf(fmaxf(qn2v + n2v - 2.f * d2, 0.f));
            float s3 = sqrtf(fmaxf(qn3  + n3v - 2.f * d3, 0.f));
            uint2 du, su;
            ((uint32_t*)&du)[0] = h2u(__floats2half2_rn(d0, d1));
            ((uint32_t*)&du)[1] = h2u(__floats2half2_rn(d2, d3));
            ((uint32_t*)&su)[0] = h2u(__floats2half2_rn(s0, s1));
            ((uint32_t*)&su)[1] = h2u(__floats2half2_rn(s2, s3));
            *(uint2*)(Hb + kk * SROW + e4 * 2)       = du;
            *(uint2*)(Hb + kk * SROW + 128 + e4 * 2) = su;
        }
    }
    __syncthreads();

    // ---- GEMM1 in two N-phases (32-reg accumulators), warps 2M x 4N of 32x32 ----
    const int m0 = (w >> 2) * 32, nw = (w & 3) * 32;
    const uint32_t aAddr = sb + OFF_H + (m0 + lrow) * SROW + lsel * 16;
    const int kt16a = (b * NK + kbase + m0) >> 4;       // ktile16 for mi=0
    const int half = (nw >> 5) & 1;                      // which half of 64-group

    #pragma unroll
    for (int ph = 1; ph >= 0; ph--) {                    // ph=1: cols 128..255 ; ph=0: cols 0..127
        const int nbase = ph * 128 + nw;
        float c1[2][4][4];
        #pragma unroll
        for (int mi = 0; mi < 2; mi++)
            #pragma unroll
            for (int ni = 0; ni < 4; ni++)
                #pragma unroll
                for (int z = 0; z < 4; z++) c1[mi][ni][z] = 0.f;

        const uint4* __restrict__ w1f = g_W1f + (nbase >> 4) * 32 + lane;
        #pragma unroll 2
        for (int ks = 0; ks < 8; ks++) {
            uint32_t a[2][4];
            ldsm4(a[0], aAddr + ks * 32);
            ldsm4(a[1], aAddr + 16 * SROW + ks * 32);
            #pragma unroll
            for (int p = 0; p < 2; p++) {
                uint4 f = w1f[ks * 512 + p * 32];
                mma16(c1[0][2 * p],     a[0], f.x, f.y);
                mma16(c1[1][2 * p],     a[1], f.x, f.y);
                mma16(c1[0][2 * p + 1], a[0], f.z, f.w);
                mma16(c1[1][2 * p + 1], a[1], f.z, f.w);
            }
        }

        if (ph == 0) __syncthreads();    // phase-B epilogue overwrites X: wait for all X reads

        // ---- epilogue: h = fp16(silu(D1 + Aq + Bk)) for this 128-col phase ----
        #pragma unroll
        for (int mi = 0; mi < 2; mi++) {
            const int r0 = m0 + mi * 16 + g, r1 = r0 + 8;
            const uint4* __restrict__ bp =
                g_Bkp + ((size_t)((kt16a + mi) * 4 + (nbase >> 6)) * 32 + lane) * 4;
            uint4 u0 = bp[half], u1 = bp[2 + half];
            const __half2* he0 = (const __half2*)&u0;
            const __half2* he1 = (const __half2*)&u1;
            #pragma unroll
            for (int ni = 0; ni < 4; ni++) {
                int f0 = nbase + 8 * ni + 2 * t;
                float2 aq = *(const float2*)(Aqs + f0);
                float2 e0 = __half22float2(he0[ni]);
                float2 e1 = __half22float2(he1[ni]);
                float v00 = silu_f(c1[mi][ni][0] + aq.x + e0.x);
                float v01 = silu_f(c1[mi][ni][1] + aq.y + e0.y);
                float v10 = silu_f(c1[mi][ni][2] + aq.x + e1.x);
                float v11 = silu_f(c1[mi][ni][3] + aq.y + e1.y);
                *(__half2*)(Hb + r0 * SROW + f0 * 2) = __floats2half2_rn(v00, v01);
                *(__half2*)(Hb + r1 * SROW + f0 * 2) = __floats2half2_rn(v10, v11);
            }
        }
    }
    __syncthreads();

    // ---- GEMM2: [64x256] @ [256x64], warps 4M x 2N, B from global fragments ----
    const int m2 = (w >> 1) * 16, n2 = (w & 1) * 32;
    float c2[4][4];
    #pragma unroll
    for (int ni = 0; ni < 4; ni++)
        #pragma unroll
        for (int z = 0; z < 4; z++) c2[ni][z] = 0.f;

    const uint32_t a2Addr = sb + OFF_H + (m2 + lrow) * SROW + lsel * 16;
    const uint4* __restrict__ w2f = g_W2f + (w & 1) * 64 + lane;

    #pragma unroll 4
    for (int ks = 0; ks < 16; ks++) {
        uint32_t a[4];
        ldsm4(a, a2Addr + ks * 32);
        #pragma unroll
        for (int p = 0; p < 2; p++) {
            uint4 f = w2f[ks * 128 + p * 32];
            mma16(c2[2 * p],     a, f.x, f.y);
            mma16(c2[2 * p + 1], a, f.z, f.w);
        }
    }

    // ---- epilogue 2: + b2 -> out ----
    const size_t obase = ((size_t)bq * NK + kbase) * DOUT;
    #pragma unroll
    for (int ni = 0; ni < 4; ni++) {
        int o = n2 + 8 * ni + 2 * t;
        int r0 = m2 + g, r1 = r0 + 8;
        *(float2*)(out + obase + (size_t)r0 * DOUT + o) =
            make_float2(c2[ni][0] + b2s[o], c2[ni][1] + b2s[o + 1]);
        *(float2*)(out + obase + (size_t)r1 * DOUT + o) =
            make_float2(c2[ni][2] + b2s[o], c2[ni][3] + b2s[o + 1]);
    }
}

// ---------------- launcher ----------------
extern "C" void kernel_launch(void* const* d_in, const int* in_sizes, int n_in,
                              void* d_out, int out_size) {
    const float* q_equi = (const float*)d_in[0];
    const float* q_inv  = (const float*)d_in[1];
    const float* k_equi = (const float*)d_in[2];
    const float* k_inv  = (const float*)d_in[3];
    const float* Wq     = (const float*)d_in[4];
    const float* bq     = (const float*)d_in[5];
    const float* Wk     = (const float*)d_in[6];
    const float* bk     = (const float*)d_in[7];
    const float* W1     = (const float*)d_in[8];
    const float* b1     = (const float*)d_in[9];
    const float* W2     = (const float*)d_in[10];
    const float* b2     = (const float*)d_in[11];
    float* out = (float*)d_out;

    cudaFuncSetAttribute(pm_main, cudaFuncAttributeMaxDynamicSharedMemorySize, SMEM_BYTES);

    prep_all<<<2 * BB * NQ + 24, 256>>>(q_inv, Wq, bq, W1, b1, k_inv, Wk, bk, W2);
    pm_main<<<dim3(NK / KT, NQ, BB), 256, SMEM_BYTES>>>(q_equi, k_equi, b2, out);
}